// round 14
// baseline (speedup 1.0000x reference)
#include <cuda_runtime.h>
#include <cuda_bf16.h>

// out[i] = sin(in[i,0]) * sin(in[i,1]); N = 16777216 rows.
// Persistent single-wave grid (148x8 CTAs x 256 thr), software-pipelined:
// iteration k+1's 2x LDG.256 are issued before iteration k's compute+store,
// keeping loads permanently in flight and decoupling store drain from load
// issue. Stores are STG.256 L2::evict_first (output must not displace input).

__device__ __forceinline__ void ld256(const float4* p, float4& q0, float4& q1) {
    unsigned long long a, b, c, d;
    asm("ld.global.nc.v4.b64 {%0,%1,%2,%3}, [%4];"
        : "=l"(a), "=l"(b), "=l"(c), "=l"(d) : "l"(p));
    q0.x = __uint_as_float((unsigned)a); q0.y = __uint_as_float((unsigned)(a >> 32));
    q0.z = __uint_as_float((unsigned)b); q0.w = __uint_as_float((unsigned)(b >> 32));
    q1.x = __uint_as_float((unsigned)c); q1.y = __uint_as_float((unsigned)(c >> 32));
    q1.z = __uint_as_float((unsigned)d); q1.w = __uint_as_float((unsigned)(d >> 32));
}

__device__ __forceinline__ unsigned long long pack2(float lo, float hi) {
    return (unsigned long long)__float_as_uint(lo)
         | ((unsigned long long)__float_as_uint(hi) << 32);
}

__device__ __forceinline__ void st256_ef(float4* p,
                                         const float4& r0, const float4& r1) {
    unsigned long long a = pack2(r0.x, r0.y);
    unsigned long long b = pack2(r0.z, r0.w);
    unsigned long long c = pack2(r1.x, r1.y);
    unsigned long long d = pack2(r1.z, r1.w);
    asm volatile("st.global.L2::evict_first.v4.b64 [%0], {%1,%2,%3,%4};"
                 :: "l"(p), "l"(a), "l"(b), "l"(c), "l"(d) : "memory");
}

__device__ __forceinline__ void compute8(const float4& p0, const float4& p1,
                                         const float4& p2, const float4& p3,
                                         float4& r0, float4& r1) {
    r0.x = __sinf(p0.x) * __sinf(p0.y);
    r0.y = __sinf(p0.z) * __sinf(p0.w);
    r0.z = __sinf(p1.x) * __sinf(p1.y);
    r0.w = __sinf(p1.z) * __sinf(p1.w);
    r1.x = __sinf(p2.x) * __sinf(p2.y);
    r1.y = __sinf(p2.z) * __sinf(p2.w);
    r1.z = __sinf(p3.x) * __sinf(p3.y);
    r1.w = __sinf(p3.z) * __sinf(p3.w);
}

__global__ __launch_bounds__(256) void sin_prod_kernel(
    const float4* __restrict__ in,   // pairs: .x=a,.y=b,.z=a',.w=b'
    float4* __restrict__ out,
    int n8)                          // number of 8-row groups = N/8
{
    int stride = gridDim.x * blockDim.x;
    int i = blockIdx.x * blockDim.x + threadIdx.x;
    if (i >= n8) return;

    // prologue: issue first iteration's loads
    float4 p0, p1, p2, p3;
    ld256(in + 4 * (size_t)i + 0, p0, p1);
    ld256(in + 4 * (size_t)i + 2, p2, p3);

    for (;;) {
        int inext = i + stride;
        float4 q0, q1, q2, q3;
        if (inext < n8) {
            // prefetch next iteration before computing/storing current
            ld256(in + 4 * (size_t)inext + 0, q0, q1);
            ld256(in + 4 * (size_t)inext + 2, q2, q3);
        }

        float4 r0, r1;
        compute8(p0, p1, p2, p3, r0, r1);
        st256_ef(out + 2 * (size_t)i, r0, r1);

        if (inext >= n8) break;
        p0 = q0; p1 = q1; p2 = q2; p3 = q3;
        i = inext;
    }
}

extern "C" void kernel_launch(void* const* d_in, const int* in_sizes, int n_in,
                              void* d_out, int out_size)
{
    const float* in = (const float*)d_in[0];
    float* out = (float*)d_out;

    int n = out_size;          // rows (16777216), divisible by 8
    int n8 = n / 8;            // 2097152 groups

    // persistent single-wave grid: 148 SMs x 8 CTAs x 256 threads
    int threads = 256;
    int blocks = 148 * 8;      // 1184
    sin_prod_kernel<<<blocks, threads>>>(
        (const float4*)in, (float4*)out, n8);
}

// round 15
// speedup vs baseline: 1.0490x; 1.0490x over previous
#include <cuda_runtime.h>
#include <cuda_bf16.h>

// out[i] = sin(in[i,0]) * sin(in[i,1]); N = 16777216 rows.
// R13 structure (best: 27.1us): persistent single-wave grid, per iteration
//   2x LDG.256 (ld.global.nc.v4.b64) -> 8 sin-pairs -> 1x STG.256 evict_first.
// Single change vs R13: 512-thread blocks x 4 CTAs/SM (same 64 warps/SM,
// half the CTA scheduling churn).

__device__ __forceinline__ void ld256(const float4* p, float4& q0, float4& q1) {
    unsigned long long a, b, c, d;
    asm("ld.global.nc.v4.b64 {%0,%1,%2,%3}, [%4];"
        : "=l"(a), "=l"(b), "=l"(c), "=l"(d) : "l"(p));
    q0.x = __uint_as_float((unsigned)a); q0.y = __uint_as_float((unsigned)(a >> 32));
    q0.z = __uint_as_float((unsigned)b); q0.w = __uint_as_float((unsigned)(b >> 32));
    q1.x = __uint_as_float((unsigned)c); q1.y = __uint_as_float((unsigned)(c >> 32));
    q1.z = __uint_as_float((unsigned)d); q1.w = __uint_as_float((unsigned)(d >> 32));
}

__device__ __forceinline__ unsigned long long pack2(float lo, float hi) {
    return (unsigned long long)__float_as_uint(lo)
         | ((unsigned long long)__float_as_uint(hi) << 32);
}

__device__ __forceinline__ void st256_ef(float4* p,
                                         const float4& r0, const float4& r1) {
    unsigned long long a = pack2(r0.x, r0.y);
    unsigned long long b = pack2(r0.z, r0.w);
    unsigned long long c = pack2(r1.x, r1.y);
    unsigned long long d = pack2(r1.z, r1.w);
    asm volatile("st.global.L2::evict_first.v4.b64 [%0], {%1,%2,%3,%4};"
                 :: "l"(p), "l"(a), "l"(b), "l"(c), "l"(d) : "memory");
}

__global__ __launch_bounds__(512) void sin_prod_kernel(
    const float4* __restrict__ in,   // pairs: .x=a,.y=b,.z=a',.w=b'
    float4* __restrict__ out,
    int n8)                          // number of 8-row groups = N/8
{
    int stride = gridDim.x * blockDim.x;
    for (int i = blockIdx.x * blockDim.x + threadIdx.x; i < n8; i += stride) {
        const float4* pin = in + 4 * (size_t)i;   // 64B per group

        float4 p0, p1, p2, p3;
        ld256(pin + 0, p0, p1);
        ld256(pin + 2, p2, p3);

        float4 r0, r1;
        r0.x = __sinf(p0.x) * __sinf(p0.y);
        r0.y = __sinf(p0.z) * __sinf(p0.w);
        r0.z = __sinf(p1.x) * __sinf(p1.y);
        r0.w = __sinf(p1.z) * __sinf(p1.w);
        r1.x = __sinf(p2.x) * __sinf(p2.y);
        r1.y = __sinf(p2.z) * __sinf(p2.w);
        r1.z = __sinf(p3.x) * __sinf(p3.y);
        r1.w = __sinf(p3.z) * __sinf(p3.w);

        st256_ef(out + 2 * (size_t)i, r0, r1);
    }
}

extern "C" void kernel_launch(void* const* d_in, const int* in_sizes, int n_in,
                              void* d_out, int out_size)
{
    const float* in = (const float*)d_in[0];
    float* out = (float*)d_out;

    int n = out_size;          // rows (16777216), divisible by 8
    int n8 = n / 8;            // 2097152 groups

    // persistent single-wave grid: 148 SMs x 4 CTAs x 512 threads = 64 warps/SM
    int threads = 512;
    int blocks = 148 * 4;      // 592
    sin_prod_kernel<<<blocks, threads>>>(
        (const float4*)in, (float4*)out, n8);
}

// round 16
// speedup vs baseline: 1.0500x; 1.0010x over previous
#include <cuda_runtime.h>
#include <cuda_bf16.h>

// out[i] = sin(in[i,0]) * sin(in[i,1]); N = 16777216 rows.
// FINAL (= R13, best of 8 measured variants: 27.1us kernel / 33.25us bench).
// Persistent single-wave grid (148 SMs x 8 CTAs x 256 thr); per iteration:
//   2x LDG.256 (ld.global.nc.v4.b64) -> 8 sin-pairs (__sinf = RRO+MUFU.SIN)
//   -> 1x STG.256 with L2::evict_first (output stream must not displace
//      input lines in L2 across graph replays).
// Measured at ~75% of HBM spec = empirical ceiling for a 2:1 R/W interleaved
// stream on this part; compute/issue/L1 all <15% — memory-roofline-bound.

__device__ __forceinline__ void ld256(const float4* p, float4& q0, float4& q1) {
    unsigned long long a, b, c, d;
    asm("ld.global.nc.v4.b64 {%0,%1,%2,%3}, [%4];"
        : "=l"(a), "=l"(b), "=l"(c), "=l"(d) : "l"(p));
    q0.x = __uint_as_float((unsigned)a); q0.y = __uint_as_float((unsigned)(a >> 32));
    q0.z = __uint_as_float((unsigned)b); q0.w = __uint_as_float((unsigned)(b >> 32));
    q1.x = __uint_as_float((unsigned)c); q1.y = __uint_as_float((unsigned)(c >> 32));
    q1.z = __uint_as_float((unsigned)d); q1.w = __uint_as_float((unsigned)(d >> 32));
}

__device__ __forceinline__ unsigned long long pack2(float lo, float hi) {
    return (unsigned long long)__float_as_uint(lo)
         | ((unsigned long long)__float_as_uint(hi) << 32);
}

__device__ __forceinline__ void st256_ef(float4* p,
                                         const float4& r0, const float4& r1) {
    unsigned long long a = pack2(r0.x, r0.y);
    unsigned long long b = pack2(r0.z, r0.w);
    unsigned long long c = pack2(r1.x, r1.y);
    unsigned long long d = pack2(r1.z, r1.w);
    asm volatile("st.global.L2::evict_first.v4.b64 [%0], {%1,%2,%3,%4};"
                 :: "l"(p), "l"(a), "l"(b), "l"(c), "l"(d) : "memory");
}

__global__ __launch_bounds__(256) void sin_prod_kernel(
    const float4* __restrict__ in,   // pairs: .x=a,.y=b,.z=a',.w=b'
    float4* __restrict__ out,
    int n8)                          // number of 8-row groups = N/8
{
    int stride = gridDim.x * blockDim.x;
    for (int i = blockIdx.x * blockDim.x + threadIdx.x; i < n8; i += stride) {
        const float4* pin = in + 4 * (size_t)i;   // 64B per group

        float4 p0, p1, p2, p3;
        ld256(pin + 0, p0, p1);
        ld256(pin + 2, p2, p3);

        float4 r0, r1;
        r0.x = __sinf(p0.x) * __sinf(p0.y);
        r0.y = __sinf(p0.z) * __sinf(p0.w);
        r0.z = __sinf(p1.x) * __sinf(p1.y);
        r0.w = __sinf(p1.z) * __sinf(p1.w);
        r1.x = __sinf(p2.x) * __sinf(p2.y);
        r1.y = __sinf(p2.z) * __sinf(p2.w);
        r1.z = __sinf(p3.x) * __sinf(p3.y);
        r1.w = __sinf(p3.z) * __sinf(p3.w);

        st256_ef(out + 2 * (size_t)i, r0, r1);
    }
}

extern "C" void kernel_launch(void* const* d_in, const int* in_sizes, int n_in,
                              void* d_out, int out_size)
{
    const float* in = (const float*)d_in[0];
    float* out = (float*)d_out;

    int n = out_size;          // rows (16777216), divisible by 8
    int n8 = n / 8;            // 2097152 groups

    // persistent single-wave grid: 148 SMs x 8 CTAs x 256 threads
    int threads = 256;
    int blocks = 148 * 8;      // 1184
    sin_prod_kernel<<<blocks, threads>>>(
        (const float4*)in, (float4*)out, n8);
}